// round 1
// baseline (speedup 1.0000x reference)
#include <cuda_runtime.h>

// out[b, m] = sum_r inputs[b, r] * pmap[r, m]
// pmap has exactly one nonzero per column -> gather:
//   out[b, m] = inputs[b, idx[m]] * val[m]

#define C_IN    5120
#define N_MOVES 1858

__device__ int   g_idx[N_MOVES];
__device__ float g_val[N_MOVES];

// ---------------------------------------------------------------------------
// Kernel A: extract (row index, value) per pmap column.
// pmap is [C_IN, N_MOVES] row-major. Threads map to columns (coalesced),
// grid.y chunks the row dimension. Exactly one nonzero per column in the
// dataset => at most one thread writes each slot; no atomics needed.
// Columns with no nonzero are pre-cleared by the init kernel.
// ---------------------------------------------------------------------------
__global__ void init_map_kernel() {
    int m = blockIdx.x * blockDim.x + threadIdx.x;
    if (m < N_MOVES) {
        g_idx[m] = 0;
        g_val[m] = 0.0f;
    }
}

#define ROWS_PER_CHUNK 64

__global__ void build_map_kernel(const float* __restrict__ pmap, int rows) {
    int m = blockIdx.x * blockDim.x + threadIdx.x;
    if (m >= N_MOVES) return;
    int r0   = blockIdx.y * ROWS_PER_CHUNK;
    int rend = min(r0 + ROWS_PER_CHUNK, rows);
    for (int r = r0; r < rend; r++) {
        float v = __ldg(&pmap[(size_t)r * N_MOVES + m]);
        if (v != 0.0f) {
            g_idx[m] = r;
            g_val[m] = v;
        }
    }
}

// ---------------------------------------------------------------------------
// Kernel B: one CTA per batch row. Stage the 5120-float (20 KB) row in SMEM
// via float4 (coalesced), then gather 1858 outputs with coalesced writes.
// ---------------------------------------------------------------------------
#define GATHER_THREADS 256

__global__ __launch_bounds__(GATHER_THREADS)
void gather_kernel(const float* __restrict__ in, float* __restrict__ out) {
    __shared__ float row[C_IN];

    const int b = blockIdx.x;
    const float4* __restrict__ src = reinterpret_cast<const float4*>(in + (size_t)b * C_IN);
    float4* dst = reinterpret_cast<float4*>(row);

    #pragma unroll
    for (int i = threadIdx.x; i < C_IN / 4; i += GATHER_THREADS) {
        dst[i] = src[i];
    }
    __syncthreads();

    float* __restrict__ o = out + (size_t)b * N_MOVES;
    #pragma unroll
    for (int m = threadIdx.x; m < N_MOVES; m += GATHER_THREADS) {
        o[m] = row[g_idx[m]] * g_val[m];
    }
}

// ---------------------------------------------------------------------------
extern "C" void kernel_launch(void* const* d_in, const int* in_sizes, int n_in,
                              void* d_out, int out_size) {
    const float* inputs = (const float*)d_in[0];   // [B, 80, 8, 8] = [B, 5120]
    const float* pmap   = (const float*)d_in[1];   // [5120, 1858]
    float* out          = (float*)d_out;           // [B, 1858]

    const int B = in_sizes[0] / C_IN;

    // Build gather map from pmap (re-done every call: deterministic, cheap).
    init_map_kernel<<<(N_MOVES + 255) / 256, 256>>>();
    dim3 bgrid((N_MOVES + 255) / 256, (C_IN + ROWS_PER_CHUNK - 1) / ROWS_PER_CHUNK);
    build_map_kernel<<<bgrid, 256>>>(pmap, C_IN);

    // Gather.
    gather_kernel<<<B, GATHER_THREADS>>>(inputs, out);
}